// round 14
// baseline (speedup 1.0000x reference)
#include <cuda_runtime.h>
#include <cuda_fp16.h>
#include <cstdint>

#define DIM    1024
#define HEADS  16
#define HD     64
#define BATCH  4
#define SEQ    2048
#define MROWS  (BATCH * SEQ)            // 8192
#define QKV_ELEMS (BATCH * HEADS * SEQ * HD)  // 8388608

// 0.125 * log2(e): folded into Q so softmax is pure exp2
#define SCALE_Q 0.18033688011112042f

// ---------------------------------------------------------------------------
// Scratch (allocation-free rule: __device__ globals) — all fp16 single
// ---------------------------------------------------------------------------
__device__ __half g_Qf[QKV_ELEMS];                 // [b,h,n,d], pre-scaled
__device__ __half g_Kf[QKV_ELEMS];                 // [b,h,n,d]
__device__ __half g_Vf[QKV_ELEMS];                 // [b,h,d,n] (transposed)
__device__ __half g_xf[MROWS * DIM];               // x
__device__ __half g_wf[3 * DIM * DIM];             // {Wq,Wk,Wv}^T [n][k]
__device__ __half g_wof[DIM * DIM];                // Wo^T [n][k]
__device__ __half g_of[MROWS * DIM];               // attn out [m][h*64+d]

// ---------------------------------------------------------------------------
// helpers
// ---------------------------------------------------------------------------
__device__ __forceinline__ uint32_t smem_u32(const void* p) {
    uint32_t a;
    asm("{ .reg .u64 t; cvta.to.shared.u64 t, %1; cvt.u32.u64 %0, t; }" : "=r"(a) : "l"(p));
    return a;
}
__device__ __forceinline__ void ldsm4(uint32_t& r0, uint32_t& r1, uint32_t& r2, uint32_t& r3,
                                      uint32_t addr) {
    asm volatile("ldmatrix.sync.aligned.m8n8.x4.shared.b16 {%0,%1,%2,%3}, [%4];"
                 : "=r"(r0), "=r"(r1), "=r"(r2), "=r"(r3) : "r"(addr));
}
__device__ __forceinline__ void mma16816h(float* d, const uint32_t* a, const uint32_t* b) {
    asm volatile(
        "mma.sync.aligned.m16n8k16.row.col.f32.f16.f16.f32 "
        "{%0,%1,%2,%3}, {%4,%5,%6,%7}, {%8,%9}, {%0,%1,%2,%3};"
        : "+f"(d[0]), "+f"(d[1]), "+f"(d[2]), "+f"(d[3])
        : "r"(a[0]), "r"(a[1]), "r"(a[2]), "r"(a[3]), "r"(b[0]), "r"(b[1]));
}
__device__ __forceinline__ void cp16(uint32_t saddr, const void* gptr) {
    asm volatile("cp.async.cg.shared.global [%0], [%1], 16;" :: "r"(saddr), "l"(gptr));
}
__device__ __forceinline__ void cp_commit() {
    asm volatile("cp.async.commit_group;" ::: "memory");
}
__device__ __forceinline__ void cp_wait0() {
    asm volatile("cp.async.wait_group 0;" ::: "memory");
}
__device__ __forceinline__ void cp_wait1() {
    asm volatile("cp.async.wait_group 1;" ::: "memory");
}
__device__ __forceinline__ float ex2(float x) {
    float y;
    asm("ex2.approx.ftz.f32 %0, %1;" : "=f"(y) : "f"(x));
    return y;
}
__device__ __forceinline__ uint32_t pack_h2(float v0, float v1) {
    __half2 t = {__float2half_rn(v0), __float2half_rn(v1)};
    return *(uint32_t*)&t;
}

// ---------------------------------------------------------------------------
// Prep kernels
// ---------------------------------------------------------------------------
__global__ __launch_bounds__(256) void conv_x_kernel(const float* __restrict__ x) {
    int i = (blockIdx.x * 256 + threadIdx.x) * 4;
    float4 v = *(const float4*)(x + i);
    *(__half2*)(g_xf + i)     = {__float2half_rn(v.x), __float2half_rn(v.y)};
    *(__half2*)(g_xf + i + 2) = {__float2half_rn(v.z), __float2half_rn(v.w)};
}

__global__ __launch_bounds__(256) void transpose_conv4(const float* __restrict__ W0,
                                                       const float* __restrict__ W1,
                                                       const float* __restrict__ W2,
                                                       const float* __restrict__ W3) {
    __shared__ float t[32][33];
    const int z = blockIdx.z;
    const float* src = (z == 0) ? W0 : (z == 1) ? W1 : (z == 2) ? W2 : W3;
    __half* dst = (z < 3) ? (g_wf + (size_t)z * DIM * DIM) : g_wof;

    const int bx = blockIdx.x * 32;
    const int by = blockIdx.y * 32;
    const int x = threadIdx.x, y0 = threadIdx.y;
#pragma unroll
    for (int i = 0; i < 32; i += 8)
        t[y0 + i][x] = src[(by + y0 + i) * DIM + bx + x];
    __syncthreads();
#pragma unroll
    for (int i = 0; i < 32; i += 8) {
        float v = t[x][y0 + i];
        dst[(bx + y0 + i) * DIM + by + x] = __float2half_rn(v);
    }
}

// ---------------------------------------------------------------------------
// Plain fp16 GEMM, cp.async 3-stage, BK=32, 2 CTAs/SM (unchanged, proven).
// MODE 0: QKV epilogue (Q pre-scaled, K, V^T). MODE 1: out proj + bias.
// ---------------------------------------------------------------------------
#define GBK    32
#define GSTR   40
#define GARR   (128 * GSTR)            // 5120 elems
#define GSTAGE (2 * GARR)              // 10240 elems
#define GSM_BYTES (3 * GSTAGE * 2)     // 61440

template <int MODE, int RB>
__global__ __launch_bounds__(256, 2) void gemm_f16(
    const __half* __restrict__ A, const __half* __restrict__ B,
    float* __restrict__ outp, const float* __restrict__ bo) {
    extern __shared__ __half smq[];

    const int tid  = threadIdx.x;
    const int lane = tid & 31;
    const int wid  = tid >> 5;
    const int wm   = wid & 1;
    const int wn   = wid >> 1;
    const int col0 = blockIdx.x * 128;

    const __half* pB = B + (size_t)col0 * DIM;
    const uint32_t sbase = smem_u32(smq);

    const int a_row = (lane & 15);
    const int a_kof = (lane >> 4) << 3;
    const int b_rof = ((lane >> 4) << 3) + (lane & 7);
    const int b_kof = ((lane >> 3) & 1) << 3;

    for (int rb = 0; rb < RB; ++rb) {
        const int row0 = (blockIdx.y * RB + rb) * 128;
        const __half* pA = A + (size_t)row0 * DIM;

        float acc[4][4][4];
#pragma unroll
        for (int i = 0; i < 4; i++)
#pragma unroll
            for (int j = 0; j < 4; j++)
#pragma unroll
                for (int q = 0; q < 4; q++) acc[i][j][q] = 0.0f;

        auto issue = [&](int c, int st) {
            const int k0 = c * GBK;
            const uint32_t sst = sbase + (uint32_t)(st * GSTAGE) * 2;
#pragma unroll
            for (int it = 0; it < 2; ++it) {
                const int lin = it * 256 + tid;
                const int rr = lin >> 2;
                const int cg = (lin & 3) * 8;
                const uint32_t so = (uint32_t)(rr * GSTR + cg) * 2;
                const size_t go = (size_t)rr * DIM + k0 + cg;
                cp16(sst + so,                      pA + go);
                cp16(sst + (uint32_t)GARR * 2 + so, pB + go);
            }
            cp_commit();
        };

        issue(0, 0);
        issue(1, 1);

        const int NC = DIM / GBK;   // 32
        for (int c = 0; c < NC; ++c) {
            if (c + 1 < NC) cp_wait1(); else cp_wait0();
            __syncthreads();
            if (c + 2 < NC) issue(c + 2, (c + 2) % 3);

            const uint32_t sA = sbase + (uint32_t)((c % 3) * GSTAGE) * 2;
            const uint32_t sB = sA + (uint32_t)GARR * 2;

#pragma unroll
            for (int ks = 0; ks < GBK / 16; ++ks) {
                uint32_t bf[2][4];
#pragma unroll
                for (int p = 0; p < 2; ++p) {
                    const uint32_t off =
                        (uint32_t)(((wn * 32 + p * 16 + b_rof) * GSTR + ks * 16 + b_kof) * 2);
                    ldsm4(bf[p][0], bf[p][1], bf[p][2], bf[p][3], sB + off);
                }
#pragma unroll
                for (int mi = 0; mi < 4; ++mi) {
                    uint32_t af[4];
                    const uint32_t off =
                        (uint32_t)(((wm * 64 + mi * 16 + a_row) * GSTR + ks * 16 + a_kof) * 2);
                    ldsm4(af[0], af[1], af[2], af[3], sA + off);
#pragma unroll
                    for (int p = 0; p < 2; ++p)
#pragma unroll
                        for (int q = 0; q < 2; ++q)
                            mma16816h(acc[mi][p * 2 + q], af, &bf[p][q * 2]);
                }
            }
        }

#pragma unroll
        for (int mi = 0; mi < 4; ++mi) {
#pragma unroll
            for (int nj = 0; nj < 4; ++nj) {
                const int r = row0 + wm * 64 + mi * 16 + (lane >> 2);
                const int cgl = col0 + wn * 32 + nj * 8 + (lane & 3) * 2;
#pragma unroll
                for (int half = 0; half < 2; ++half) {
                    const int rr = r + half * 8;
                    float v0 = acc[mi][nj][half * 2 + 0];
                    float v1 = acc[mi][nj][half * 2 + 1];
                    if (MODE == 0) {
                        const int b_ = rr >> 11, n = rr & 2047;
                        const int wsel = cgl >> 10;
                        const int c1 = cgl & 1023;
                        const int h = c1 >> 6, d0 = c1 & 63;
                        if (wsel == 0) {
                            const size_t o = ((size_t)(b_ * HEADS + h) * SEQ + n) * HD + d0;
                            *(__half2*)(g_Qf + o) = {__float2half_rn(v0 * SCALE_Q),
                                                     __float2half_rn(v1 * SCALE_Q)};
                        } else if (wsel == 1) {
                            const size_t o = ((size_t)(b_ * HEADS + h) * SEQ + n) * HD + d0;
                            *(__half2*)(g_Kf + o) = {__float2half_rn(v0), __float2half_rn(v1)};
                        } else {
                            const size_t o = ((size_t)(b_ * HEADS + h) * HD + d0) * SEQ + n;
                            g_Vf[o]       = __float2half_rn(v0);
                            g_Vf[o + SEQ] = __float2half_rn(v1);
                        }
                    } else {
                        *(float2*)(outp + (size_t)rr * DIM + cgl) =
                            make_float2(v0 + bo[cgl], v1 + bo[cgl + 1]);
                    }
                }
            }
        }
        if (rb + 1 < RB) __syncthreads();
    }
}

// ---------------------------------------------------------------------------
// Flash attention, plain fp16, 128-thread CTAs (4 warps x 16 q-rows = 64 rows),
// KV chunk 64, cp.async 2-stage, Q frags in registers, 4 CTAs/SM.
// ---------------------------------------------------------------------------
#define ASTR   72
#define AQ_EL  (64 * ASTR)             // 4608 (Q staging, 64 rows)
#define KV_AR  (64 * ASTR)             // 4608 per K / V array
#define AST_EL (2 * KV_AR)             // 9216 per stage
#define A_KV0  AQ_EL                   // KV stages after Q staging
#define A_TOTAL ((A_KV0 + 2 * AST_EL) * 2)   // 46080 bytes

__global__ __launch_bounds__(128, 4) void attn_mma() {
    extern __shared__ __half sma[];

    const int bh   = blockIdx.y;
    const int rblk = blockIdx.x;       // 0..31 (64-row q tiles)
    const int tid  = threadIdx.x;
    const int lane = tid & 31;
    const int wid  = tid >> 5;         // 0..3
    const int q0   = wid * 16;

    const size_t qbase = ((size_t)bh * SEQ + rblk * 64) * HD;
    const size_t kbase = (size_t)bh * SEQ * HD;
    const size_t vbase = (size_t)bh * HD * SEQ;

    const uint32_t sbase = smem_u32(sma);

    const int a_row = lane & 15;
    const int a_kof = (lane >> 4) << 3;
    const int b_rof = ((lane >> 4) << 3) + (lane & 7);
    const int b_kof = ((lane >> 3) & 1) << 3;

    // Stage Q once (64x64), then hold fragments in registers
#pragma unroll
    for (int it = 0; it < 4; ++it) {
        const int lin = it * 128 + tid;        // 0..511 : 64 rows x 8 groups
        const int r = lin >> 3, d = (lin & 7) * 8;
        cp16(sbase + (uint32_t)(r * ASTR + d) * 2, g_Qf + qbase + (size_t)r * HD + d);
    }
    cp_commit();
    cp_wait0();
    __syncthreads();

    uint32_t qf[4][4];
#pragma unroll
    for (int ks = 0; ks < 4; ++ks) {
        const uint32_t off = (uint32_t)(((q0 + a_row) * ASTR + ks * 16 + a_kof) * 2);
        ldsm4(qf[ks][0], qf[ks][1], qf[ks][2], qf[ks][3], sbase + off);
    }

    auto issue_kv = [&](int chunk, int st) {
        const int c0 = chunk * 64;
        const uint32_t skv = sbase + (uint32_t)(A_KV0 + st * AST_EL) * 2;
#pragma unroll
        for (int it = 0; it < 4; ++it) {
            const int lin = it * 128 + tid;    // 0..511 : 64 rows x 8 groups
            const int r = lin >> 3, d = (lin & 7) * 8;
            const uint32_t so = (uint32_t)(r * ASTR + d) * 2;
            cp16(skv + so,                        g_Kf + kbase + (size_t)(c0 + r) * HD + d);
            cp16(skv + (uint32_t)KV_AR * 2 + so,  g_Vf + vbase + (size_t)r * SEQ + c0 + d);
        }
        cp_commit();
    };

    issue_kv(0, 0);

    float acc_o[8][4];
#pragma unroll
    for (int j = 0; j < 8; j++)
#pragma unroll
        for (int q = 0; q < 4; q++) acc_o[j][q] = 0.0f;
    float mi[2] = {-1e30f, -1e30f}, li[2] = {0.0f, 0.0f};

    const int NC = SEQ / 64;   // 32
    for (int c = 0; c < NC; ++c) {
        const int st = c & 1;
        cp_wait0();
        __syncthreads();
        if (c + 1 < NC) issue_kv(c + 1, st ^ 1);

        const uint32_t skv = sbase + (uint32_t)(A_KV0 + st * AST_EL) * 2;
        const uint32_t uK = skv;
        const uint32_t uV = skv + (uint32_t)KV_AR * 2;

        // --- S = Q K^T ---
        float acc_s[8][4];
#pragma unroll
        for (int j = 0; j < 8; j++)
#pragma unroll
            for (int q = 0; q < 4; q++) acc_s[j][q] = 0.0f;

#pragma unroll
        for (int ks = 0; ks < 4; ++ks) {
#pragma unroll
            for (int p = 0; p < 4; ++p) {
                uint32_t kf[4];
                const uint32_t off = (uint32_t)(((p * 16 + b_rof) * ASTR + ks * 16 + b_kof) * 2);
                ldsm4(kf[0], kf[1], kf[2], kf[3], uK + off);
#pragma unroll
                for (int q = 0; q < 2; ++q)
                    mma16816h(acc_s[p * 2 + q], qf[ks], &kf[q * 2]);
            }
        }

        // --- online softmax in exp2 domain ---
#pragma unroll
        for (int half = 0; half < 2; ++half) {
            float rmax = -1e30f;
#pragma unroll
            for (int nj = 0; nj < 8; ++nj)
#pragma unroll
                for (int t = 0; t < 2; ++t)
                    rmax = fmaxf(rmax, acc_s[nj][half * 2 + t]);
            rmax = fmaxf(rmax, __shfl_xor_sync(0xffffffffu, rmax, 1));
            rmax = fmaxf(rmax, __shfl_xor_sync(0xffffffffu, rmax, 2));
            const float mn = fmaxf(mi[half], rmax);
            float rsum = 0.0f;
#pragma unroll
            for (int nj = 0; nj < 8; ++nj)
#pragma unroll
                for (int t = 0; t < 2; ++t) {
                    const float e = ex2(acc_s[nj][half * 2 + t] - mn);
                    acc_s[nj][half * 2 + t] = e;
                    rsum += e;
                }
            rsum += __shfl_xor_sync(0xffffffffu, rsum, 1);
            rsum += __shfl_xor_sync(0xffffffffu, rsum, 2);
            const float alpha = ex2(mi[half] - mn);
            li[half] = li[half] * alpha + rsum;
            mi[half] = mn;
#pragma unroll
            for (int nj = 0; nj < 8; ++nj)
#pragma unroll
                for (int t = 0; t < 2; ++t) acc_o[nj][half * 2 + t] *= alpha;
        }

        // --- O += P V ---
#pragma unroll
        for (int ks = 0; ks < 4; ++ks) {
            uint32_t pf[4];
            pf[0] = pack_h2(acc_s[2 * ks][0],     acc_s[2 * ks][1]);
            pf[1] = pack_h2(acc_s[2 * ks][2],     acc_s[2 * ks][3]);
            pf[2] = pack_h2(acc_s[2 * ks + 1][0], acc_s[2 * ks + 1][1]);
            pf[3] = pack_h2(acc_s[2 * ks + 1][2], acc_s[2 * ks + 1][3]);
#pragma unroll
            for (int p = 0; p < 4; ++p) {
                uint32_t vf[4];
                const uint32_t off = (uint32_t)(((p * 16 + b_rof) * ASTR + ks * 16 + b_kof) * 2);
                ldsm4(vf[0], vf[1], vf[2], vf[3], uV + off);
#pragma unroll
                for (int q = 0; q < 2; ++q)
                    mma16816h(acc_o[p * 2 + q], pf, &vf[q * 2]);
            }
        }
    }

    // Epilogue: normalize, write fp16 O
    const int b_ = bh >> 4, h = bh & 15;
#pragma unroll
    for (int half = 0; half < 2; ++half) {
        const float inv = 1.0f / li[half];
        const int row = rblk * 64 + q0 + (lane >> 2) + half * 8;
        const size_t mrow = ((size_t)b_ * SEQ + row) * DIM + h * HD;
#pragma unroll
        for (int nj = 0; nj < 8; ++nj) {
            const int cc = nj * 8 + (lane & 3) * 2;
            *(__half2*)(g_of + mrow + cc) = {
                __float2half_rn(acc_o[nj][half * 2 + 0] * inv),
                __float2half_rn(acc_o[nj][half * 2 + 1] * inv)};
        }
    }
}

// ---------------------------------------------------------------------------

extern "C" void kernel_launch(void* const* d_in, const int* in_sizes, int n_in,
                              void* d_out, int out_size) {
    (void)in_sizes; (void)n_in; (void)out_size;
    const float* x  = (const float*)d_in[0];
    const float* Wq = (const float*)d_in[1];
    const float* Wk = (const float*)d_in[2];
    const float* Wv = (const float*)d_in[3];
    const float* Wo = (const float*)d_in[4];
    const float* bo = (const float*)d_in[5];
    float* out = (float*)d_out;

    cudaFuncSetAttribute((const void*)gemm_f16<0, 1>,
                         cudaFuncAttributeMaxDynamicSharedMemorySize, GSM_BYTES);
    cudaFuncSetAttribute((const void*)gemm_f16<1, 2>,
                         cudaFuncAttributeMaxDynamicSharedMemorySize, GSM_BYTES);
    cudaFuncSetAttribute((const void*)attn_mma,
                         cudaFuncAttributeMaxDynamicSharedMemorySize, A_TOTAL);

    __half *xf, *wf, *wof, *of;
    cudaGetSymbolAddress((void**)&xf,  g_xf);
    cudaGetSymbolAddress((void**)&wf,  g_wf);
    cudaGetSymbolAddress((void**)&wof, g_wof);
    cudaGetSymbolAddress((void**)&of,  g_of);

    conv_x_kernel<<<MROWS * DIM / 1024, 256>>>(x);
    transpose_conv4<<<dim3(32, 32, 4), dim3(32, 8)>>>(Wq, Wk, Wv, Wo);

    gemm_f16<0, 1><<<dim3(24, 64), 256, GSM_BYTES>>>(xf, wf, nullptr, nullptr);
    attn_mma<<<dim3(32, 64), 128, A_TOTAL>>>();
    gemm_f16<1, 2><<<dim3(8, 32), 256, GSM_BYTES>>>(of, wof, out, bo);
}